// round 14
// baseline (speedup 1.0000x reference)
#include <cuda_runtime.h>
#include <math.h>

#define NMAX 200000
#define DFEAT 256
#define MNB   64
#define KSEL  3
#define NODES_PER_WARP 8

// Scratch (allocation-free): per-node projections.
__device__ float g_s_self[NMAX];
__device__ float g_s_all[NMAX];

__device__ __forceinline__ float4 ldcs4(const float4* p) {
    return __ldcs(p);          // evict-first streaming load
}

// ---------------------------------------------------------------------------
// Kernel 1 (measured optimum, unchanged): one warp handles 8 nodes as four
// software-pipelined batches of 2. x rows loaded with __ldcs (read-once
// stream; evict-first keeps L2 clean for g_s_all, helping topk's gathers).
// ---------------------------------------------------------------------------
__global__ void __launch_bounds__(256) score_kernel(const float* __restrict__ x,
                                                    const float* __restrict__ W,
                                                    const float* __restrict__ bias,
                                                    int N) {
    int warp = (blockIdx.x * 256 + threadIdx.x) >> 5;
    int lane = threadIdx.x & 31;
    int node0 = warp * NODES_PER_WARP;
    if (node0 >= N) return;

    const float4* wa4 = (const float4*)(W);          // W[0:256]
    const float4* wb4 = (const float4*)(W + DFEAT);  // W[256:512]
    float4 a0 = __ldg(wa4 + lane), a1 = __ldg(wa4 + lane + 32);
    float4 b0 = __ldg(wb4 + lane), b1 = __ldg(wb4 + lane + 32);
    float bb = bias[0];

    float4 cur[4];
#pragma unroll
    for (int i = 0; i < 2; i++) {
        int n = node0 + i;
        if (n < N) {
            const float4* xr = (const float4*)(x + (size_t)n * DFEAT);
            cur[2 * i]     = ldcs4(xr + lane);
            cur[2 * i + 1] = ldcs4(xr + lane + 32);
        }
    }

#pragma unroll
    for (int batch = 0; batch < NODES_PER_WARP; batch += 2) {
        int nb0 = node0 + batch;

        float4 nxt[4];
        if (batch + 2 < NODES_PER_WARP) {            // prefetch next 2 nodes
#pragma unroll
            for (int i = 0; i < 2; i++) {
                int n = nb0 + 2 + i;
                if (n < N) {
                    const float4* xr = (const float4*)(x + (size_t)n * DFEAT);
                    nxt[2 * i]     = ldcs4(xr + lane);
                    nxt[2 * i + 1] = ldcs4(xr + lane + 32);
                }
            }
        }

        float sa[2], sb[2];
#pragma unroll
        for (int i = 0; i < 2; i++) {
            float4 c0 = cur[2 * i], c1 = cur[2 * i + 1];
            float ta, tb;
            ta  = c0.x * a0.x;          ta = fmaf(c0.y, a0.y, ta);
            ta  = fmaf(c0.z, a0.z, ta); ta = fmaf(c0.w, a0.w, ta);
            ta  = fmaf(c1.x, a1.x, ta); ta = fmaf(c1.y, a1.y, ta);
            ta  = fmaf(c1.z, a1.z, ta); ta = fmaf(c1.w, a1.w, ta);
            tb  = c0.x * b0.x;          tb = fmaf(c0.y, b0.y, tb);
            tb  = fmaf(c0.z, b0.z, tb); tb = fmaf(c0.w, b0.w, tb);
            tb  = fmaf(c1.x, b1.x, tb); tb = fmaf(c1.y, b1.y, tb);
            tb  = fmaf(c1.w, b1.w, tb); tb = fmaf(c1.z, b1.z, tb);
            sa[i] = ta; sb[i] = tb;
        }

#pragma unroll
        for (int off = 16; off; off >>= 1) {
#pragma unroll
            for (int i = 0; i < 2; i++) {
                sa[i] += __shfl_xor_sync(0xffffffffu, sa[i], off);
                sb[i] += __shfl_xor_sync(0xffffffffu, sb[i], off);
            }
        }
        if (lane == 0) {
#pragma unroll
            for (int i = 0; i < 2; i++) {
                int n = nb0 + i;
                if (n < N) {
                    g_s_self[n] = sa[i] + bb;
                    g_s_all[n]  = sb[i];
                }
            }
        }

        if (batch + 2 < NODES_PER_WARP) {
#pragma unroll
            for (int j = 0; j < 4; j++) cur[j] = nxt[j];
        }
    }
}

// Order-preserving float<->uint mapping (total order on floats).
__device__ __forceinline__ unsigned fkey(float f) {
    unsigned u = __float_as_uint(f);
    return (u & 0x80000000u) ? ~u : (u | 0x80000000u);
}
__device__ __forceinline__ float funkey(unsigned u) {
    unsigned b = (u & 0x80000000u) ? (u & 0x7fffffffu) : ~u;
    return __uint_as_float(b);
}

// ---------------------------------------------------------------------------
// Kernel 2 (round-12 measured-best structure restored): FOUR nodes per warp
// (8-lane segments), 8 candidate slots/lane, unsigned-key Batcher-8 presort,
// head-pop rounds (REDUX.max + ballot + ffs, winner stores id directly).
// New: neighbors/counts read with __ldcs (read-once streams; evict-first
// protects g_s_all's L2 residency, which every gather depends on).
// ---------------------------------------------------------------------------
__global__ void __launch_bounds__(256) topk_kernel(const int* __restrict__ neighbors,
                                                   const int* __restrict__ counts,
                                                   float* __restrict__ out,
                                                   int N) {
    int warp = (blockIdx.x * 256 + threadIdx.x) >> 5;
    int lane = threadIdx.x & 31;
    int seg  = lane >> 3;                 // segment id within warp (0..3)
    int sub  = lane & 7;                  // lane within segment
    int node = warp * 4 + seg;
    if (node >= N) return;

    unsigned mask = 0xFFu << (seg * 8);

    int cnt  = __ldcs(counts + node);
    int base = sub * 8;

    const int4* nb = (const int4*)(neighbors + (size_t)node * MNB);
    int4 nA = __ldcs(nb + sub * 2);        // positions base..base+3
    int4 nB = __ldcs(nb + sub * 2 + 1);    // positions base+4..base+7

    unsigned k[8];
    int      c[8];
    c[0] = nA.x; c[1] = nA.y; c[2] = nA.z; c[3] = nA.w;
    c[4] = nB.x; c[5] = nB.y; c[6] = nB.z; c[7] = nB.w;
    // key 0 marks invalid; fkey(any float) > 0. Predicated-off gathers emit
    // no L1 wavefront. cnt >= K so the top-3 are always real entries.
#pragma unroll
    for (int i = 0; i < 8; i++)
        k[i] = (base + i < cnt) ? fkey(__ldg(g_s_all + c[i])) : 0u;

    // Batcher odd-even mergesort for 8, descending (max kept at lower index).
#define CSWAP(i, j)                                                     \
    { bool sw = k[j] > k[i];                                            \
      unsigned tk = sw ? k[j] : k[i]; k[j] = sw ? k[i] : k[j]; k[i] = tk; \
      int tc = sw ? c[j] : c[i]; c[j] = sw ? c[i] : c[j]; c[i] = tc; }
    CSWAP(0,1) CSWAP(2,3) CSWAP(4,5) CSWAP(6,7)
    CSWAP(0,2) CSWAP(1,3) CSWAP(4,6) CSWAP(5,7)
    CSWAP(1,2) CSWAP(5,6)
    CSWAP(0,4) CSWAP(1,5) CSWAP(2,6) CSWAP(3,7)
    CSWAP(2,4) CSWAP(3,5)
    CSWAP(1,2) CSWAP(3,4) CSWAP(5,6)
#undef CSWAP

    float* osel = out + (size_t)N * KSEL;
    size_t ob = (size_t)node * KSEL;

    unsigned w0, w1, w2;
#pragma unroll
    for (int t = 0; t < KSEL; t++) {
        unsigned m = __reduce_max_sync(mask, k[0]);
        unsigned bal = __ballot_sync(mask, k[0] == m);  // non-mask bits are 0
        int wl = __ffs((int)bal) - 1;                   // absolute lane id

        if (t == 0) w0 = m; else if (t == 1) w1 = m; else w2 = m;

        if (lane == wl) {                               // winner: store id, pop
            osel[ob + t] = (float)c[0];                 // exact: ids < 2^24
#pragma unroll
            for (int i = 0; i < 7; i++) { k[i] = k[i + 1]; c[i] = c[i + 1]; }
        }
    }

    if (sub < KSEL) {                                   // parallel value epilogue
        unsigned wk = (sub == 0) ? w0 : (sub == 1) ? w1 : w2;
        float v = g_s_self[node] + funkey(wk);
        v = fmaxf(v, 0.01f * v);                        // leaky_relu (jax default)
        out[ob + sub] = __expf(v);
    }
}

extern "C" void kernel_launch(void* const* d_in, const int* in_sizes, int n_in,
                              void* d_out, int out_size) {
    // metadata order: node_features, neighbors, neighbor_counts, W, b
    const float* x         = (const float*)d_in[0];
    const int*   neighbors = (const int*)d_in[1];
    const int*   counts    = (const int*)d_in[2];
    const float* W         = (const float*)d_in[3];
    const float* bias      = (const float*)d_in[4];

    int N = in_sizes[0] / DFEAT;
    if (N > NMAX) N = NMAX;

    int warps1  = (N + NODES_PER_WARP - 1) / NODES_PER_WARP;
    int blocks1 = (warps1 + 7) / 8;
    score_kernel<<<blocks1, 256>>>(x, W, bias, N);

    int warps2  = (N + 3) / 4;               // 4 nodes per warp
    int blocks2 = (warps2 + 7) / 8;
    topk_kernel<<<blocks2, 256>>>(neighbors, counts, (float*)d_out, N);
}